// round 11
// baseline (speedup 1.0000x reference)
#include <cuda_runtime.h>

#define Bv 64
#define Tv 2048
#define Nv 128

__device__ __forceinline__ void ffma2(unsigned long long& d,
                                      unsigned long long a,
                                      unsigned long long b) {
    asm("fma.rn.f32x2 %0, %1, %2, %0;" : "+l"(d) : "l"(a), "l"(b));
}
__device__ __forceinline__ void fadd2(unsigned long long& d, unsigned long long a) {
    asm("add.rn.f32x2 %0, %0, %1;" : "+l"(d) : "l"(a));
}
__device__ __forceinline__ unsigned long long pack2(float a, float b) {
    unsigned long long r;
    asm("mov.b64 %0, {%1, %2};" : "=l"(r) : "f"(a), "f"(b));
    return r;
}
__device__ __forceinline__ float2 unpack2(unsigned long long v) {
    float2 r;
    asm("mov.b64 {%0, %1}, %2;" : "=f"(r.x), "=f"(r.y) : "l"(v));
    return r;
}
__device__ __forceinline__ float lo32(unsigned long long v) {
    float r;
    asm("{ .reg .f32 hi; mov.b64 {%0, hi}, %1; }" : "=f"(r) : "l"(v));
    return r;
}

// One CTA per batch; thread n owns output tag n.
// Scaled linear space: alpha_t[n] = logM + log(W_t[n]); exact power-of-2 rescale.
// Per-step dot product uses an explicit double-buffered W-load pipeline
// (4 groups x 8 LDS.128) and 8 accumulator chains so every shared load after
// the first group has its latency covered by the FFMA2 issue stream.
__global__ __launch_bounds__(Nv, 1)
void crf_fwd(const float* __restrict__ emissions,
             const int* __restrict__ token_sizes,
             const float* __restrict__ transitions,
             const float* __restrict__ head,
             const float* __restrict__ last,
             float* __restrict__ out)
{
    const int b = blockIdx.x;
    const int n = threadIdx.x;

    __shared__ __align__(16) float W[2][Nv];
    __shared__ float red[4];

    // Pack column n of exp(transitions) as 64 f32x2 register pairs.
    unsigned long long e2[Nv / 2];
    #pragma unroll
    for (int k = 0; k < Nv / 2; ++k) {
        float lo = __expf(transitions[(2 * k + 0) * Nv + n]);
        float hi = __expf(transitions[(2 * k + 1) * Nv + n]);
        e2[k] = pack2(lo, hi);
    }

    const int len = token_sizes[b];
    const float* em = emissions + (size_t)b * Tv * Nv + n;

    // t = 0: alpha0 = head + em[0]; normalize by K = alpha0[0].
    float a0 = head[n] + em[0];
    W[0][n] = a0;
    __syncthreads();
    float K = W[0][0];
    float logM = K;
    W[1][n] = __expf(a0 - K);
    __syncthreads();
    int p = 1;

    // Depth-2 raw-emission prefetch.
    float ex = __expf(em[Nv]);                    // exp(em) for t = 1
    float nx = em[min(2, Tv - 1) * Nv];           // raw em for t = 2

    for (int t = 1; t < len; ++t) {
        const ulonglong2* Wv = reinterpret_cast<const ulonglong2*>(W[p]);

        // Group 0 loads (8 LDS.128) issued first, right after the barrier.
        ulonglong2 wb0[8], wb1[8];
        #pragma unroll
        for (int i = 0; i < 8; ++i) wb0[i] = Wv[i];

        // Rescale factor from W[p][0] (available as soon as wb0[0] lands).
        float w0 = lo32(wb0[0].x);
        int ebits = __float_as_int(w0) & 0x7f800000;
        float m = ex * __int_as_float(0x7f000000 - ebits);   // ex * 2^(127-E)
        logM += (float)((ebits >> 23) - 127) * 0.693147180559945f;

        unsigned long long s0 = 0ull, s1 = 0ull, s2 = 0ull, s3 = 0ull;
        unsigned long long s4 = 0ull, s5 = 0ull, s6 = 0ull, s7 = 0ull;

        // Pipelined groups: load group g+1 while consuming group g.
        #pragma unroll
        for (int g = 0; g < 4; ++g) {
            ulonglong2* cur = (g & 1) ? wb1 : wb0;
            ulonglong2* nxt = (g & 1) ? wb0 : wb1;
            if (g < 3) {
                #pragma unroll
                for (int i = 0; i < 8; ++i) nxt[i] = Wv[8 * (g + 1) + i];
            }
            #pragma unroll
            for (int i = 0; i < 8; ++i) {
                int k = 8 * g + i;             // pair-of-pairs index
                ffma2((i & 4) ? ((i & 2) ? s6 : s4) : ((i & 2) ? s2 : s0),
                      cur[i].x, e2[2 * k]);
                ffma2((i & 4) ? ((i & 2) ? s7 : s5) : ((i & 2) ? s3 : s1),
                      cur[i].y, e2[2 * k + 1]);
            }
        }

        fadd2(s0, s1); fadd2(s2, s3); fadd2(s4, s5); fadd2(s6, s7);
        fadd2(s0, s2); fadd2(s4, s6); fadd2(s0, s4);
        float2 sp = unpack2(s0);
        float s = sp.x + sp.y;

        W[p ^ 1][n] = s * m;

        // Advance emission pipeline (clamped; value unused past len).
        ex = __expf(nx);
        nx = em[min(t + 2, Tv - 1) * Nv];

        __syncthreads();
        p ^= 1;
    }

    // Finalize: out = logM + log(sum_n W[n] * exp(last[n]))
    float term = W[p][n] * __expf(last[n]);
    #pragma unroll
    for (int o = 16; o > 0; o >>= 1)
        term += __shfl_down_sync(0xffffffffu, term, o);
    if ((n & 31) == 0) red[n >> 5] = term;
    __syncthreads();
    if (n == 0) {
        float tot = (red[0] + red[1]) + (red[2] + red[3]);
        out[b] = logM + logf(tot);
    }
}

extern "C" void kernel_launch(void* const* d_in, const int* in_sizes, int n_in,
                              void* d_out, int out_size) {
    const float* emissions   = (const float*)d_in[0];
    const int*   token_sizes = (const int*)d_in[1];
    const float* transitions = (const float*)d_in[2];
    const float* head        = (const float*)d_in[3];
    const float* last        = (const float*)d_in[4];
    crf_fwd<<<Bv, Nv>>>(emissions, token_sizes, transitions, head, last,
                        (float*)d_out);
}

// round 12
// speedup vs baseline: 1.9283x; 1.9283x over previous
#include <cuda_runtime.h>

#define Bv 64
#define Tv 2048
#define Nv 128

// Scratch for the two half-scans (device globals: no allocation allowed).
__device__ float g_W[2][Bv][Nv];     // [0]=forward alpha_mid, [1]=backward beta_mid (scaled linear)
__device__ float g_logM[2][Bv];

__device__ __forceinline__ void ffma2(unsigned long long& d,
                                      unsigned long long a,
                                      unsigned long long b) {
    asm("fma.rn.f32x2 %0, %1, %2, %0;" : "+l"(d) : "l"(a), "l"(b));
}
__device__ __forceinline__ void fadd2(unsigned long long& d, unsigned long long a) {
    asm("add.rn.f32x2 %0, %0, %1;" : "+l"(d) : "l"(a));
}
__device__ __forceinline__ unsigned long long pack2(float a, float b) {
    unsigned long long r;
    asm("mov.b64 %0, {%1, %2};" : "=l"(r) : "f"(a), "f"(b));
    return r;
}
__device__ __forceinline__ float2 unpack2(unsigned long long v) {
    float2 r;
    asm("mov.b64 {%0, %1}, %2;" : "=f"(r.x), "=f"(r.y) : "l"(v));
    return r;
}
__device__ __forceinline__ float lo32(unsigned long long v) {
    float r;
    asm("{ .reg .f32 hi; mov.b64 {%0, hi}, %1; }" : "=f"(r) : "l"(v));
    return r;
}

// 128-tap packed dot product against smem vector Wp; also returns Wp[0] (w0)
// from the first LDS.128 for the power-of-2 rescale.
__device__ __forceinline__ float dot128(const float* Wp,
                                        const unsigned long long (&e2)[Nv / 2],
                                        float& w0) {
    const ulonglong2* Wv = reinterpret_cast<const ulonglong2*>(Wp);
    ulonglong2 w = Wv[0];
    w0 = lo32(w.x);
    unsigned long long s0 = 0ull, s1 = 0ull, s2 = 0ull, s3 = 0ull;
    ffma2(s0, w.x, e2[0]);
    ffma2(s1, w.y, e2[1]);
    #pragma unroll
    for (int k = 1; k < Nv / 4; ++k) {
        w = Wv[k];
        if ((k & 1) == 0) { ffma2(s0, w.x, e2[2 * k]); ffma2(s1, w.y, e2[2 * k + 1]); }
        else              { ffma2(s2, w.x, e2[2 * k]); ffma2(s3, w.y, e2[2 * k + 1]); }
    }
    fadd2(s0, s1); fadd2(s2, s3); fadd2(s0, s2);
    float2 sp = unpack2(s0);
    return sp.x + sp.y;
}

// Exact power-of-2 rescale factor from w0's exponent; accumulates logM.
__device__ __forceinline__ float inv_scale(float w0, float& logM) {
    int ebits = __float_as_int(w0) & 0x7f800000;
    logM += (float)((ebits >> 23) - 127) * 0.693147180559945f;
    return __int_as_float(0x7f000000 - ebits);   // 2^(127 - E)
}

// 128 CTAs: blockIdx < 64 runs the FORWARD half-scan of batch b (alpha_0..alpha_mid),
// blockIdx >= 64 runs the BACKWARD half-scan (beta_{len-1}..beta_mid). Both use the
// scaled-linear-space matvec; forward threads hold COLUMNS of E=exp(trans), backward
// threads hold ROWS. Results meet at t=mid; a tiny combine kernel finishes.
__global__ __launch_bounds__(Nv, 1)
void crf_half(const float* __restrict__ emissions,
              const int* __restrict__ token_sizes,
              const float* __restrict__ transitions,
              const float* __restrict__ head,
              const float* __restrict__ last)
{
    const int dir = blockIdx.x >> 6;        // 0 = forward, 1 = backward
    const int b   = blockIdx.x & 63;
    const int n   = threadIdx.x;

    __shared__ __align__(16) float W[2][Nv];

    const int len = token_sizes[b];
    const int mid = len >> 1;
    const float* em = emissions + (size_t)b * Tv * Nv + n;

    // Packed E operands: forward = column n (E[j][n] over j), backward = row n.
    unsigned long long e2[Nv / 2];
    if (dir == 0) {
        #pragma unroll
        for (int k = 0; k < Nv / 2; ++k)
            e2[k] = pack2(__expf(transitions[(2 * k + 0) * Nv + n]),
                          __expf(transitions[(2 * k + 1) * Nv + n]));
    } else {
        #pragma unroll
        for (int k = 0; k < Nv / 2; ++k)
            e2[k] = pack2(__expf(transitions[n * Nv + 2 * k + 0]),
                          __expf(transitions[n * Nv + 2 * k + 1]));
    }

    float logM;
    int p = 1;

    if (dir == 0) {
        // ---------------- forward: alpha_0 .. alpha_mid ----------------
        float a0 = head[n] + em[0];
        W[0][n] = a0;
        __syncthreads();
        float K = W[0][0];
        logM = K;
        W[1][n] = __expf(a0 - K);
        __syncthreads();

        float ex = __expf(em[Nv]);                    // exp(em_1)
        float nx = em[min(2, Tv - 1) * Nv];

        for (int t = 1; t <= mid; ++t) {
            float w0;
            float s = dot128(W[p], e2, w0);
            float m = ex * inv_scale(w0, logM);
            W[p ^ 1][n] = s * m;
            ex = __expf(nx);
            nx = em[min(t + 2, Tv - 1) * Nv];
            __syncthreads();
            p ^= 1;
        }
    } else {
        // ---------------- backward: beta_{len-1} .. beta_mid ----------------
        // Stored vector carries the ex of the NEXT step to consume; the final
        // produced beta_mid excludes ex_mid (alpha_mid already includes em_mid).
        const bool has_step = (len - 1 > mid);        // always true for len >= 3
        float b0 = last[n] + (has_step ? em[(size_t)(len - 1) * Nv] : 0.0f);
        W[0][n] = b0;
        __syncthreads();
        float K = W[0][0];
        logM = K;
        W[1][n] = __expf(b0 - K);
        __syncthreads();

        float ex = __expf(em[(size_t)max(len - 2, 0) * Nv]);   // exp(em_{len-2})
        float nx = em[(size_t)max(len - 3, 0) * Nv];

        for (int t = len - 1; t > mid; --t) {
            float w0;
            float s = dot128(W[p], e2, w0);
            float exm = (t - 1 > mid) ? ex : 1.0f;    // last step: no emission factor
            float m = exm * inv_scale(w0, logM);
            W[p ^ 1][n] = s * m;
            ex = __expf(nx);
            nx = em[(size_t)max(t - 4, 0) * Nv];
            __syncthreads();
            p ^= 1;
        }
    }

    g_W[dir][b][n] = W[p][n];
    if (n == 0) g_logM[dir][b] = logM;
}

// Combine: out[b] = logMf + logMb + log( sum_n Wf[n] * Wb[n] )
__global__ __launch_bounds__(Nv, 1)
void crf_combine(float* __restrict__ out)
{
    const int b = blockIdx.x;
    const int n = threadIdx.x;
    __shared__ float red[4];

    float term = g_W[0][b][n] * g_W[1][b][n];
    #pragma unroll
    for (int o = 16; o > 0; o >>= 1)
        term += __shfl_down_sync(0xffffffffu, term, o);
    if ((n & 31) == 0) red[n >> 5] = term;
    __syncthreads();
    if (n == 0) {
        float tot = (red[0] + red[1]) + (red[2] + red[3]);
        out[b] = g_logM[0][b] + g_logM[1][b] + logf(tot);
    }
}

extern "C" void kernel_launch(void* const* d_in, const int* in_sizes, int n_in,
                              void* d_out, int out_size) {
    const float* emissions   = (const float*)d_in[0];
    const int*   token_sizes = (const int*)d_in[1];
    const float* transitions = (const float*)d_in[2];
    const float* head        = (const float*)d_in[3];
    const float* last        = (const float*)d_in[4];
    crf_half<<<2 * Bv, Nv>>>(emissions, token_sizes, transitions, head, last);
    crf_combine<<<Bv, Nv>>>((float*)d_out);
}